// round 1
// baseline (speedup 1.0000x reference)
#include <cuda_runtime.h>
#include <cuda_bf16.h>

// Implicit-GEMM 3x3 SAME conv:
//   out[n,k,p,q] = sum_{c,kh,kw} x[n,c,p+kh-1,q+kw-1] * W[k, c*9+kh*3+kw] + perturbs[n,k,p,q]
// GEMM view: A = W [128 x 1152], B = im2col(x) [1152 x (32*64*64)], block tile 128x64.
// One block = one (n, p) output row: all 128 channels x 64 q-positions.

#define KC   16
#define RTOT 1152   // C*9 = 128*9

__global__ __launch_bounds__(256)
void conv3x3_kernel(const float* __restrict__ x,
                    const float* __restrict__ W,
                    const float* __restrict__ per,
                    float* __restrict__ out) {
    const int bid = blockIdx.x;      // n*64 + p
    const int n = bid >> 6;
    const int p = bid & 63;
    const int t = threadIdx.x;
    const int tm = t >> 4;           // 0..15 -> 8 output channels each
    const int tn = t & 15;           // 0..15 -> 4 q-positions each

    __shared__ float As[KC][128];    // [r][k]
    __shared__ float Bs[KC][64];     // [r][q]

    float acc[8][4];
    #pragma unroll
    for (int i = 0; i < 8; i++)
        #pragma unroll
        for (int j = 0; j < 4; j++) acc[i][j] = 0.f;

    // B-load indices (fixed per thread): rr = t/16, j0 = (t%16)*4
    const int b_rr = t >> 4;
    const int b_j0 = (t & 15) << 2;

    for (int r0 = 0; r0 < RTOT; r0 += KC) {
        // ---- load A chunk: W[k, r0..r0+15] -> As[r][k] ----
        #pragma unroll
        for (int u = 0; u < 2; u++) {
            int f  = t + u * 256;            // 512 float4 pieces total
            int k  = f >> 2;                 // 0..127
            int c4 = (f & 3) << 2;           // 0,4,8,12 within chunk
            float4 w4 = *reinterpret_cast<const float4*>(W + k * RTOT + r0 + c4);
            As[c4 + 0][k] = w4.x;
            As[c4 + 1][k] = w4.y;
            As[c4 + 2][k] = w4.z;
            As[c4 + 3][k] = w4.w;
        }
        // ---- load B chunk: im2col gather with zero padding ----
        {
            int r   = r0 + b_rr;
            int c   = r / 9;
            int t9  = r - c * 9;
            int kh  = t9 / 3;
            int kw  = t9 - kh * 3;
            int row = p + kh - 1;
            bool vrow = ((unsigned)row < 64u);
            const float* xp = x + (((long)(n * 128 + c)) * 64 + row) * 64;
            #pragma unroll
            for (int i = 0; i < 4; i++) {
                int q = b_j0 + i + kw - 1;
                Bs[b_rr][b_j0 + i] = (vrow && (unsigned)q < 64u) ? __ldg(xp + q) : 0.f;
            }
        }
        __syncthreads();

        // ---- compute: 16 outer products of 8x4 ----
        #pragma unroll
        for (int rr = 0; rr < KC; rr++) {
            float4 b  = *reinterpret_cast<const float4*>(&Bs[rr][tn << 2]);
            float4 a0 = *reinterpret_cast<const float4*>(&As[rr][tm << 3]);
            float4 a1 = *reinterpret_cast<const float4*>(&As[rr][(tm << 3) + 4]);
            float av[8] = {a0.x, a0.y, a0.z, a0.w, a1.x, a1.y, a1.z, a1.w};
            float bv[4] = {b.x, b.y, b.z, b.w};
            #pragma unroll
            for (int i = 0; i < 8; i++)
                #pragma unroll
                for (int j = 0; j < 4; j++)
                    acc[i][j] = fmaf(av[i], bv[j], acc[i][j]);
        }
        __syncthreads();
    }

    // ---- epilogue: add perturbs, store ----
    #pragma unroll
    for (int i = 0; i < 8; i++) {
        int k = (tm << 3) + i;
        int q = tn << 2;
        long off = ((((long)n * 128 + k)) * 64 + p) * 64 + q;
        float4 pv = *reinterpret_cast<const float4*>(per + off);
        float4 o;
        o.x = acc[i][0] + pv.x;
        o.y = acc[i][1] + pv.y;
        o.z = acc[i][2] + pv.z;
        o.w = acc[i][3] + pv.w;
        *reinterpret_cast<float4*>(out + off) = o;
    }
}

extern "C" void kernel_launch(void* const* d_in, const int* in_sizes, int n_in,
                              void* d_out, int out_size) {
    const float* x   = (const float*)d_in[0];   // (32,128,64,64)
    const float* W   = (const float*)d_in[1];   // (128,1152)
    const float* per = (const float*)d_in[2];   // (32,128,64,64)
    float* out = (float*)d_out;                 // (32,128,64,64)

    dim3 grid(32 * 64);   // one block per (n, p) row
    dim3 block(256);
    conv3x3_kernel<<<grid, block>>>(x, W, per, out);
}

// round 4
// speedup vs baseline: 1.3951x; 1.3951x over previous
#include <cuda_runtime.h>
#include <cstdint>

// ============================================================================
// tf32 mma.sync (HMMA) implicit-GEMM 3x3 SAME conv + bias(perturbs)
//   out[n,k,p,q] = sum_{c,kh,kw} x[n,c,p+kh-1,q+kw-1]*W[k,c*9+kh*3+kw] + per
// 9 shifted 1x1 convs x 4 c-chunks of 32 => 36 K-stages.
// CTA: 128 out-channels x 128 pixels (2 p-rows x 64 q). 8 warps, warp tile 64x32.
// mma.sync.aligned.m16n8k8 tf32 (plain sm_103 target — no tcgen05 needed).
// A (W) prepacked in per-thread fragment order (LDS.128 per fragment).
// B (x) cp.async with zero-fill borders; rows padded to 136 floats.
// ============================================================================

#define NSTAGES 36

// Prepacked W fragments: [stage36][j4][mtile8][lane32][reg4] tf32 bits
static __device__ __align__(128) unsigned WtFrag[NSTAGES * 4 * 8 * 32 * 4];

__global__ void prepack_kernel(const float* __restrict__ W) {
    int idx = blockIdx.x * 256 + threadIdx.x;
    if (idx >= NSTAGES * 4096) return;
    int reg  = idx & 3;
    int lane = (idx >> 2) & 31;
    int mt   = (idx >> 7) & 7;
    int j    = (idx >> 10) & 3;
    int s    = idx >> 12;            // stage
    int shift = s >> 2;              // 0..8
    int chunk = s & 3;               // 0..3
    int dr = (reg & 1) ? 8 : 0;
    int dk = (reg & 2) ? 4 : 0;
    int r  = (lane >> 2) + dr;       // row within 16
    int kc = (lane & 3) + dk;        // col within 8
    int k  = mt * 16 + r;
    int c  = chunk * 32 + j * 8 + kc;
    float v = W[k * 1152 + c * 9 + shift];
    unsigned u;
    asm("cvt.rna.tf32.f32 %0, %1;" : "=r"(u) : "f"(v));
    WtFrag[idx] = u;
}

// Stage layout in dynamic smem (per buffer):
//   A: 16384 B  (4 j * 8 mt * 32 lane * 16 B, fragment-ordered)
//   B: 32 rows * 136 floats * 4 = 17408 B
#define A_BYTES   16384
#define B_PITCH_F 136
#define B_BYTES   (32 * B_PITCH_F * 4)
#define STAGE_B   (A_BYTES + B_BYTES)
#define DYN_SMEM  (2 * STAGE_B)

__device__ __forceinline__ uint32_t smem_u32(const void* p) {
    uint32_t a;
    asm("{ .reg .u64 t; cvta.to.shared.u64 t, %1; cvt.u32.u64 %0, t; }" : "=r"(a) : "l"(p));
    return a;
}

__device__ __forceinline__ void mma_tf32(float* c, const unsigned* a, const unsigned* b) {
    asm volatile(
        "mma.sync.aligned.m16n8k8.row.col.f32.tf32.tf32.f32 "
        "{%0,%1,%2,%3}, {%4,%5,%6,%7}, {%8,%9}, {%0,%1,%2,%3};"
        : "+f"(c[0]), "+f"(c[1]), "+f"(c[2]), "+f"(c[3])
        : "r"(a[0]), "r"(a[1]), "r"(a[2]), "r"(a[3]), "r"(b[0]), "r"(b[1]));
}

__global__ __launch_bounds__(256, 2)
void conv_mma_kernel(const float* __restrict__ x,
                     const float* __restrict__ per,
                     float* __restrict__ out) {
    extern __shared__ char smem[];
    const uint32_t sb = smem_u32(smem);

    const int tid  = threadIdx.x;
    const int lane = tid & 31;
    const int w    = tid >> 5;
    const int wm   = w >> 2;          // 0..1 -> M base wm*64
    const int wn   = w & 3;           // 0..3 -> px base wn*32
    const int gid  = lane >> 2;
    const int tig  = lane & 3;

    const int n  = blockIdx.x >> 5;
    const int p0 = (blockIdx.x & 31) << 1;   // 2 p-rows per CTA

    const float* xn = x + (size_t)n * 128 * 4096;

    // cp.async thread mapping for B: cc = tid/8 (c within chunk), sub = tid%8
    const int b_cc  = tid >> 3;
    const int b_sub = tid & 7;

    float acc[4][4][4];
    #pragma unroll
    for (int mt = 0; mt < 4; mt++)
        #pragma unroll
        for (int nt = 0; nt < 4; nt++)
            #pragma unroll
            for (int e = 0; e < 4; e++) acc[mt][nt][e] = 0.f;

    // ------------- copy issue for one stage -------------
    auto issue_stage = [&](int s, int buf) {
        const uint32_t a_s = sb + buf * STAGE_B;
        const uint32_t b_s = a_s + A_BYTES;
        // A: linear fragment-ordered 16KB
        {
            const char* src = ((const char*)WtFrag) + (size_t)s * A_BYTES + tid * 64;
            uint32_t dst = a_s + tid * 64;
            #pragma unroll
            for (int u = 0; u < 4; u++)
                asm volatile("cp.async.cg.shared.global [%0], [%1], 16;"
                             :: "r"(dst + u * 16), "l"(src + u * 16));
        }
        // B: 32 c-rows x 128 px, zero-filled borders
        {
            const int shift = s >> 2, chunk = s & 3;
            const int kh = shift / 3, kw = shift - 3 * (shift / 3);
            const int px0  = b_sub << 4;               // 16 consecutive px
            const int prow = px0 >> 6;
            const int row  = p0 + prow + kh - 1;
            const bool vrow = ((unsigned)row < 64u);
            const int c = (chunk << 5) + b_cc;
            const float* srow = xn + (size_t)c * 4096 + row * 64;
            const uint32_t drow = b_s + (b_cc * B_PITCH_F + px0) * 4;
            const int q0 = (px0 & 63) + kw - 1;
            if (kw == 1) {
                const int pb = vrow ? 16 : 0;
                #pragma unroll
                for (int u = 0; u < 4; u++)
                    asm volatile("cp.async.cg.shared.global [%0], [%1], 16, %2;"
                                 :: "r"(drow + u * 16), "l"(srow + q0 + u * 4), "r"(pb));
            } else {
                #pragma unroll
                for (int i = 0; i < 16; i++) {
                    const int q = q0 + i;
                    const int pb = (vrow && (unsigned)q < 64u) ? 4 : 0;
                    asm volatile("cp.async.ca.shared.global [%0], [%1], 4, %2;"
                                 :: "r"(drow + i * 4), "l"(srow + q), "r"(pb));
                }
            }
        }
        asm volatile("cp.async.commit_group;");
    };

    // ------------- compute one stage -------------
    auto compute_stage = [&](int buf) {
        const uint32_t a_s = sb + buf * STAGE_B;
        const uint32_t b_s = a_s + A_BYTES;
        #pragma unroll
        for (int j = 0; j < 4; j++) {
            unsigned afr[4][4];
            #pragma unroll
            for (int mt = 0; mt < 4; mt++) {
                const uint32_t addr = a_s + (((j << 3) + (wm << 2) + mt) << 9) + (lane << 4);
                asm volatile("ld.shared.v4.b32 {%0,%1,%2,%3}, [%4];"
                             : "=r"(afr[mt][0]), "=r"(afr[mt][1]),
                               "=r"(afr[mt][2]), "=r"(afr[mt][3])
                             : "r"(addr));
            }
            unsigned bfr[4][2];
            #pragma unroll
            for (int nt = 0; nt < 4; nt++) {
                const uint32_t addr = b_s +
                    (((j << 3) + tig) * B_PITCH_F + (wn << 5) + (nt << 3) + gid) * 4;
                float f0, f1;
                asm volatile("ld.shared.f32 %0, [%1];" : "=f"(f0) : "r"(addr));
                asm volatile("ld.shared.f32 %0, [%1];" : "=f"(f1)
                             : "r"(addr + 4 * B_PITCH_F * 4));
                asm("cvt.rna.tf32.f32 %0, %1;" : "=r"(bfr[nt][0]) : "f"(f0));
                asm("cvt.rna.tf32.f32 %0, %1;" : "=r"(bfr[nt][1]) : "f"(f1));
            }
            #pragma unroll
            for (int mt = 0; mt < 4; mt++)
                #pragma unroll
                for (int nt = 0; nt < 4; nt++)
                    mma_tf32(acc[mt][nt], afr[mt], bfr[nt]);
        }
    };

    // ------------- pipeline -------------
    issue_stage(0, 0);
    for (int i = 0; i < NSTAGES; i++) {
        if (i + 1 < NSTAGES) {
            issue_stage(i + 1, (i + 1) & 1);
            asm volatile("cp.async.wait_group 1;");
        } else {
            asm volatile("cp.async.wait_group 0;");
        }
        __syncthreads();
        compute_stage(i & 1);
        __syncthreads();
    }

    // ------------- epilogue: registers -> +perturbs -> out -------------
    const size_t nbase = (size_t)n * 128 * 4096;
    #pragma unroll
    for (int mt = 0; mt < 4; mt++) {
        #pragma unroll
        for (int nt = 0; nt < 4; nt++) {
            const int px = (wn << 5) + (nt << 3) + (tig << 1);
            const int prow = px >> 6;
            const int q = px & 63;
            #pragma unroll
            for (int h = 0; h < 2; h++) {
                const int k = (wm << 6) + (mt << 4) + gid + (h << 3);
                const size_t o = nbase + (size_t)k * 4096 + (p0 + prow) * 64 + q;
                float2 pv = *reinterpret_cast<const float2*>(per + o);
                float2 ov;
                ov.x = acc[mt][nt][h * 2 + 0] + pv.x;
                ov.y = acc[mt][nt][h * 2 + 1] + pv.y;
                *reinterpret_cast<float2*>(out + o) = ov;
            }
        }
    }
}

extern "C" void kernel_launch(void* const* d_in, const int* in_sizes, int n_in,
                              void* d_out, int out_size) {
    const float* x   = (const float*)d_in[0];   // (32,128,64,64)
    const float* W   = (const float*)d_in[1];   // (128,1152)
    const float* per = (const float*)d_in[2];   // (32,128,64,64)
    float* out = (float*)d_out;

    cudaFuncSetAttribute(conv_mma_kernel,
                         cudaFuncAttributeMaxDynamicSharedMemorySize, DYN_SMEM);

    prepack_kernel<<<(NSTAGES * 4096 + 255) / 256, 256>>>(W);
    conv_mma_kernel<<<1024, 256, DYN_SMEM>>>(x, per, out);
}

// round 6
// speedup vs baseline: 3.1457x; 2.2549x over previous
#include <cuda_runtime.h>
#include <cstdint>

// ============================================================================
// tf32 mma.sync implicit-GEMM 3x3 SAME conv + bias, x-row-resident version.
// CTA: 128 out-channels x 128 px (2 p-rows x 64 q). 8 warps.
// Reduction: 4 c-chunks of 32; per chunk, x strip (32c x 4rows x 66cols w/ halo)
// lives in smem; all 9 shifts read it with (kh,kw) offsets. 2 barriers/chunk.
// W prepacked in per-thread mma-fragment order, read by LDG.128 from L2.
// ============================================================================

#define NSTAGES 36

// [stage36][j4][mtile8][lane32][reg4] tf32 bits
static __device__ __align__(128) unsigned WtFrag[NSTAGES * 4 * 8 * 32 * 4];

__global__ void prepack_kernel(const float* __restrict__ W) {
    int idx = blockIdx.x * 256 + threadIdx.x;
    if (idx >= NSTAGES * 4096) return;
    int reg  = idx & 3;
    int lane = (idx >> 2) & 31;
    int mt   = (idx >> 7) & 7;
    int j    = (idx >> 10) & 3;
    int s    = idx >> 12;            // stage = shift*4 + chunk
    int shift = s >> 2;
    int chunk = s & 3;
    int dr = (reg & 1) ? 8 : 0;
    int dk = (reg & 2) ? 4 : 0;
    int r  = (lane >> 2) + dr;
    int kc = (lane & 3) + dk;
    int k  = mt * 16 + r;
    int c  = chunk * 32 + j * 8 + kc;
    float v = W[k * 1152 + c * 9 + shift];
    unsigned u;
    asm("cvt.rna.tf32.f32 %0, %1;" : "=r"(u) : "f"(v));
    WtFrag[idx] = u;
}

// x strip buffer: [c32*4rows][66 cols], col = q+1 (halo at 0 and 65)
#define XS_PITCH  66
#define XS_BUF_F  (32 * 4 * XS_PITCH)      // 8448 floats
#define XS_BUF_B  (XS_BUF_F * 4)           // 33792 bytes
#define DYN_SMEM  (2 * XS_BUF_B)           // 67584

__device__ __forceinline__ uint32_t smem_u32(const void* p) {
    uint32_t a;
    asm("{ .reg .u64 t; cvta.to.shared.u64 t, %1; cvt.u32.u64 %0, t; }" : "=r"(a) : "l"(p));
    return a;
}

__device__ __forceinline__ void mma_tf32(float* c, const unsigned* a, const unsigned* b) {
    asm volatile(
        "mma.sync.aligned.m16n8k8.row.col.f32.tf32.tf32.f32 "
        "{%0,%1,%2,%3}, {%4,%5,%6,%7}, {%8,%9}, {%0,%1,%2,%3};"
        : "+f"(c[0]), "+f"(c[1]), "+f"(c[2]), "+f"(c[3])
        : "r"(a[0]), "r"(a[1]), "r"(a[2]), "r"(a[3]), "r"(b[0]), "r"(b[1]));
}

__global__ __launch_bounds__(256, 2)
void conv_mma_kernel(const float* __restrict__ x,
                     const float* __restrict__ per,
                     float* __restrict__ out) {
    extern __shared__ char smem[];
    const uint32_t sb = smem_u32(smem);

    const int tid  = threadIdx.x;
    const int lane = tid & 31;
    const int w    = tid >> 5;
    const int wm   = w >> 2;           // 0..1
    const int wn   = w & 3;            // 0..3
    const int gid  = lane >> 2;        // 0..7  (n within 8)
    const int tig  = lane & 3;         // 0..3  (k within 8, rows tig & tig+4)
    const int prow = wn >> 1;          // p-row of this warp's px range

    const int n  = blockIdx.x >> 5;
    const int p0 = (blockIdx.x & 31) << 1;

    const float* xn = x + (size_t)n * 128 * 4096;

    // ---- zero halo columns (col 0 and 65 of every (c,row), both buffers) ----
    {
        // 2 bufs * 128 (c*4+row) pairs = 256 == blockDim
        const int buf = tid >> 7, rem = tid & 127;
        const uint32_t a = sb + buf * XS_BUF_B + rem * (XS_PITCH * 4);
        asm volatile("st.shared.f32 [%0], %1;" :: "r"(a), "f"(0.f));
        asm volatile("st.shared.f32 [%0], %1;" :: "r"(a + 65 * 4), "f"(0.f));
    }

    // ---- chunk prefetch: 32 4B cp.async per thread ----
    const int f_c   = tid >> 3;        // 0..31 (c within chunk)
    const int f_r   = (tid >> 1) & 3;  // 0..3  (buffer row)
    const int f_q0  = (tid & 1) << 5;  // 0 or 32
    const int f_row = p0 - 1 + f_r;    // global p row
    const int f_pb  = ((unsigned)f_row < 64u) ? 4 : 0;

    auto prefetch = [&](int chunk, int buf) {
        const float* src = xn + (size_t)((chunk << 5) + f_c) * 4096 + f_row * 64 + f_q0;
        uint32_t dst = sb + buf * XS_BUF_B +
                       (((f_c << 2) + f_r) * XS_PITCH + 1 + f_q0) * 4;
        #pragma unroll
        for (int i = 0; i < 32; i++)
            asm volatile("cp.async.ca.shared.global [%0], [%1], 4, %2;"
                         :: "r"(dst + i * 4), "l"(src + i), "r"(f_pb));
        asm volatile("cp.async.commit_group;");
    };

    prefetch(0, 0);
    prefetch(1, 1);

    float acc[4][4][4];
    #pragma unroll
    for (int mt = 0; mt < 4; mt++)
        #pragma unroll
        for (int nt = 0; nt < 4; nt++)
            #pragma unroll
            for (int e = 0; e < 4; e++) acc[mt][nt][e] = 0.f;

    for (int chunk = 0; chunk < 4; chunk++) {
        if (chunk < 3) asm volatile("cp.async.wait_group 1;");
        else           asm volatile("cp.async.wait_group 0;");
        __syncthreads();

        const uint32_t xb = sb + (chunk & 1) * XS_BUF_B;
        // base B addr (floats): ((tig*4 + prow)*66 + (wn&1)*32 + gid)
        const uint32_t bbase = xb +
            (((tig << 2) + prow) * XS_PITCH + ((wn & 1) << 5) + gid) * 4;

        #pragma unroll
        for (int shift = 0; shift < 9; shift++) {
            const int kh = shift / 3, kw = shift - 3 * (shift / 3);
            const int s = (shift << 2) + chunk;
            const uint32_t bsh = bbase + (kh * XS_PITCH + kw) * 4;
            const uint4* ap0 = (const uint4*)WtFrag +
                               (((size_t)s << 2) * 8 + (wm << 2)) * 32 + lane;
            #pragma unroll
            for (int j = 0; j < 4; j++) {
                unsigned a[4][4];
                #pragma unroll
                for (int mt = 0; mt < 4; mt++) {
                    uint4 v = __ldg(ap0 + ((size_t)j * 8 + mt) * 32);
                    a[mt][0] = v.x; a[mt][1] = v.y; a[mt][2] = v.z; a[mt][3] = v.w;
                }
                unsigned b[4][2];
                const uint32_t bj = bsh + j * 8448;   // j*8 c-rows * 264 floats
                #pragma unroll
                for (int nt = 0; nt < 4; nt++) {
                    float f0, f1;
                    asm volatile("ld.shared.f32 %0, [%1];" : "=f"(f0)
                                 : "r"(bj + (nt << 5)));
                    asm volatile("ld.shared.f32 %0, [%1];" : "=f"(f1)
                                 : "r"(bj + (nt << 5) + 4224));  // +4 c-rows
                    asm("cvt.rna.tf32.f32 %0, %1;" : "=r"(b[nt][0]) : "f"(f0));
                    asm("cvt.rna.tf32.f32 %0, %1;" : "=r"(b[nt][1]) : "f"(f1));
                }
                #pragma unroll
                for (int mt = 0; mt < 4; mt++)
                    #pragma unroll
                    for (int nt = 0; nt < 4; nt++)
                        mma_tf32(acc[mt][nt], a[mt], b[nt]);
            }
        }
        __syncthreads();
        if (chunk + 2 < 4) prefetch(chunk + 2, chunk & 1);
    }

    // ---- epilogue: +perturbs, store (same mapping as validated R4 kernel) ----
    const size_t nbase = (size_t)n * 128 * 4096;
    #pragma unroll
    for (int mt = 0; mt < 4; mt++) {
        #pragma unroll
        for (int nt = 0; nt < 4; nt++) {
            const int px = (wn << 5) + (nt << 3) + (tig << 1);
            const int pr = px >> 6;
            const int q  = px & 63;
            #pragma unroll
            for (int h = 0; h < 2; h++) {
                const int k = (wm << 6) + (mt << 4) + gid + (h << 3);
                const size_t o = nbase + (size_t)k * 4096 + (p0 + pr) * 64 + q;
                float2 pv = *reinterpret_cast<const float2*>(per + o);
                float2 ov;
                ov.x = acc[mt][nt][h * 2 + 0] + pv.x;
                ov.y = acc[mt][nt][h * 2 + 1] + pv.y;
                *reinterpret_cast<float2*>(out + o) = ov;
            }
        }
    }
}

extern "C" void kernel_launch(void* const* d_in, const int* in_sizes, int n_in,
                              void* d_out, int out_size) {
    const float* x   = (const float*)d_in[0];   // (32,128,64,64)
    const float* W   = (const float*)d_in[1];   // (128,1152)
    const float* per = (const float*)d_in[2];   // (32,128,64,64)
    float* out = (float*)d_out;

    cudaFuncSetAttribute(conv_mma_kernel,
                         cudaFuncAttributeMaxDynamicSharedMemorySize, DYN_SMEM);

    prepack_kernel<<<(NSTAGES * 4096 + 255) / 256, 256>>>(W);
    conv_mma_kernel<<<1024, 256, DYN_SMEM>>>(x, per, out);
}

// round 7
// speedup vs baseline: 3.2597x; 1.0363x over previous
#include <cuda_runtime.h>
#include <cstdint>

// ============================================================================
// tf32 mma.sync implicit-GEMM 3x3 SAME conv + bias, x-row-resident.
// CTA: 128 out-channels x 128 px (2 p-rows x 64 q). 8 warps, warp tile 64x32.
// Per c-chunk (32 c): x strip (32c x 4rows x 66cols, halo cols zeroed) in smem;
// all 9 shifts read it at (kh,kw) offsets. W prepacked in mma-fragment order,
// streamed via double-buffered register prefetch (LDG.128). B fed to tf32 MMA
// as raw f32 bits (HW truncation) — no cvt in the inner loop.
// ============================================================================

#define NSTAGES 36

// [stage36][j4][mtile8][lane32][reg4] tf32 bits
static __device__ __align__(128) unsigned WtFrag[NSTAGES * 4 * 8 * 32 * 4];

__global__ void prepack_kernel(const float* __restrict__ W) {
    int idx = blockIdx.x * 256 + threadIdx.x;
    if (idx >= NSTAGES * 4096) return;
    int reg  = idx & 3;
    int lane = (idx >> 2) & 31;
    int mt   = (idx >> 7) & 7;
    int j    = (idx >> 10) & 3;
    int s    = idx >> 12;            // stage = shift*4 + chunk
    int shift = s >> 2;
    int chunk = s & 3;
    int dr = (reg & 1) ? 8 : 0;
    int dk = (reg & 2) ? 4 : 0;
    int r  = (lane >> 2) + dr;
    int kc = (lane & 3) + dk;
    int k  = mt * 16 + r;
    int c  = chunk * 32 + j * 8 + kc;
    float v = W[k * 1152 + c * 9 + shift];
    unsigned u;
    asm("cvt.rna.tf32.f32 %0, %1;" : "=r"(u) : "f"(v));
    WtFrag[idx] = u;
}

// x strip buffer: [c32*4rows][66 cols], col = q+1 (halo at 0 and 65)
#define XS_PITCH  66
#define XS_BUF_F  (32 * 4 * XS_PITCH)
#define XS_BUF_B  (XS_BUF_F * 4)           // 33792 bytes
#define DYN_SMEM  (2 * XS_BUF_B)           // 67584

__device__ __forceinline__ uint32_t smem_u32(const void* p) {
    uint32_t a;
    asm("{ .reg .u64 t; cvta.to.shared.u64 t, %1; cvt.u32.u64 %0, t; }" : "=r"(a) : "l"(p));
    return a;
}

__device__ __forceinline__ void mma_tf32(float* c, const unsigned* a, const unsigned* b) {
    asm volatile(
        "mma.sync.aligned.m16n8k8.row.col.f32.tf32.tf32.f32 "
        "{%0,%1,%2,%3}, {%4,%5,%6,%7}, {%8,%9}, {%0,%1,%2,%3};"
        : "+f"(c[0]), "+f"(c[1]), "+f"(c[2]), "+f"(c[3])
        : "r"(a[0]), "r"(a[1]), "r"(a[2]), "r"(a[3]), "r"(b[0]), "r"(b[1]));
}

__global__ __launch_bounds__(256, 2)
void conv_mma_kernel(const float* __restrict__ x,
                     const float* __restrict__ per,
                     float* __restrict__ out) {
    extern __shared__ char smem[];
    const uint32_t sb = smem_u32(smem);

    const int tid  = threadIdx.x;
    const int lane = tid & 31;
    const int w    = tid >> 5;
    const int wm   = w >> 2;           // 0..1
    const int wn   = w & 3;            // 0..3
    const int gid  = lane >> 2;        // 0..7
    const int tig  = lane & 3;         // 0..3
    const int prow = wn >> 1;

    const int n  = blockIdx.x >> 5;
    const int p0 = (blockIdx.x & 31) << 1;

    const float* xn = x + (size_t)n * 128 * 4096;

    // ---- zero halo columns (col 0 and 65 of every (c,row), both buffers) ----
    {
        const int buf = tid >> 7, rem = tid & 127;
        const uint32_t a = sb + buf * XS_BUF_B + rem * (XS_PITCH * 4);
        asm volatile("st.shared.f32 [%0], %1;" :: "r"(a), "f"(0.f));
        asm volatile("st.shared.f32 [%0], %1;" :: "r"(a + 65 * 4), "f"(0.f));
    }

    // ---- chunk prefetch: 32 4B cp.async per thread ----
    const int f_c   = tid >> 3;
    const int f_r   = (tid >> 1) & 3;
    const int f_q0  = (tid & 1) << 5;
    const int f_row = p0 - 1 + f_r;
    const int f_pb  = ((unsigned)f_row < 64u) ? 4 : 0;

    auto prefetch = [&](int chunk, int buf) {
        const float* src = xn + (size_t)((chunk << 5) + f_c) * 4096 + f_row * 64 + f_q0;
        uint32_t dst = sb + buf * XS_BUF_B +
                       (((f_c << 2) + f_r) * XS_PITCH + 1 + f_q0) * 4;
        #pragma unroll
        for (int i = 0; i < 32; i++)
            asm volatile("cp.async.ca.shared.global [%0], [%1], 4, %2;"
                         :: "r"(dst + i * 4), "l"(src + i), "r"(f_pb));
        asm volatile("cp.async.commit_group;");
    };

    prefetch(0, 0);
    prefetch(1, 1);

    float acc[4][4][4];
    #pragma unroll
    for (int mt = 0; mt < 4; mt++)
        #pragma unroll
        for (int nt = 0; nt < 4; nt++)
            #pragma unroll
            for (int e = 0; e < 4; e++) acc[mt][nt][e] = 0.f;

    for (int chunk = 0; chunk < 4; chunk++) {
        if (chunk < 3) asm volatile("cp.async.wait_group 1;");
        else           asm volatile("cp.async.wait_group 0;");
        __syncthreads();

        const uint32_t xb = sb + (chunk & 1) * XS_BUF_B;
        const uint32_t bbase = xb +
            (((tig << 2) + prow) * XS_PITCH + ((wn & 1) << 5) + gid) * 4;
        // A fragment base (uint4 units): chunk*1024 + wm*128 + lane
        const uint4* abase = (const uint4*)WtFrag + (chunk << 10) + (wm << 7) + lane;

        unsigned areg[2][4][4];
        #pragma unroll
        for (int mt = 0; mt < 4; mt++) {
            uint4 v = __ldg(abase + mt * 32);     // jj=0 offset = 0
            areg[0][mt][0] = v.x; areg[0][mt][1] = v.y;
            areg[0][mt][2] = v.z; areg[0][mt][3] = v.w;
        }

        #pragma unroll
        for (int jj = 0; jj < 36; jj++) {
            const int shift = jj >> 2, j = jj & 3;
            const int kh = shift / 3, kw = shift - 3 * kh;
            const int cur = jj & 1, nxt = cur ^ 1;

            // prefetch A fragments for jj+1 (compile-time offsets)
            if (jj < 35) {
                const int jn = jj + 1;
                const int aoff = (jn >> 2) * 4096 + (jn & 3) * 256;  // uint4 units
                #pragma unroll
                for (int mt = 0; mt < 4; mt++) {
                    uint4 v = __ldg(abase + aoff + mt * 32);
                    areg[nxt][mt][0] = v.x; areg[nxt][mt][1] = v.y;
                    areg[nxt][mt][2] = v.z; areg[nxt][mt][3] = v.w;
                }
            }

            // B fragments: raw f32 bits (tf32 truncation in HW)
            const uint32_t bj = bbase + (kh * XS_PITCH + kw) * 4 + j * 8448;
            unsigned b[4][2];
            #pragma unroll
            for (int nt = 0; nt < 4; nt++) {
                asm volatile("ld.shared.b32 %0, [%1];" : "=r"(b[nt][0])
                             : "r"(bj + (nt << 5)));
                asm volatile("ld.shared.b32 %0, [%1];" : "=r"(b[nt][1])
                             : "r"(bj + (nt << 5) + 4224));
            }

            #pragma unroll
            for (int mt = 0; mt < 4; mt++)
                #pragma unroll
                for (int nt = 0; nt < 4; nt++)
                    mma_tf32(acc[mt][nt], areg[cur][mt], b[nt]);
        }

        __syncthreads();
        if (chunk + 2 < 4) prefetch(chunk + 2, chunk & 1);
    }

    // ---- epilogue: +perturbs, store ----
    const size_t nbase = (size_t)n * 128 * 4096;
    #pragma unroll
    for (int mt = 0; mt < 4; mt++) {
        #pragma unroll
        for (int nt = 0; nt < 4; nt++) {
            const int px = (wn << 5) + (nt << 3) + (tig << 1);
            const int pr = px >> 6;
            const int q  = px & 63;
            #pragma unroll
            for (int h = 0; h < 2; h++) {
                const int k = (wm << 6) + (mt << 4) + gid + (h << 3);
                const size_t o = nbase + (size_t)k * 4096 + (p0 + pr) * 64 + q;
                float2 pv = *reinterpret_cast<const float2*>(per + o);
                float2 ov;
                ov.x = acc[mt][nt][h * 2 + 0] + pv.x;
                ov.y = acc[mt][nt][h * 2 + 1] + pv.y;
                *reinterpret_cast<float2*>(out + o) = ov;
            }
        }
    }
}

extern "C" void kernel_launch(void* const* d_in, const int* in_sizes, int n_in,
                              void* d_out, int out_size) {
    const float* x   = (const float*)d_in[0];   // (32,128,64,64)
    const float* W   = (const float*)d_in[1];   // (128,1152)
    const float* per = (const float*)d_in[2];   // (32,128,64,64)
    float* out = (float*)d_out;

    cudaFuncSetAttribute(conv_mma_kernel,
                         cudaFuncAttributeMaxDynamicSharedMemorySize, DYN_SMEM);

    prepack_kernel<<<(NSTAGES * 4096 + 255) / 256, 256>>>(W);
    conv_mma_kernel<<<1024, 256, DYN_SMEM>>>(x, per, out);
}

// round 11
// speedup vs baseline: 4.5340x; 1.3909x over previous
#include <cuda_runtime.h>
#include <cstdint>

// ============================================================================
// tf32 mma.sync implicit-GEMM 3x3 SAME conv + bias, x-row-resident,
// A-register-reuse version.
// CTA: 128 out-channels x 256 px (4 p-rows x 64 q). 8 warps; warp = 64k x 64px
// (two 32-px halves sharing the A registers => halves A traffic per MMA).
// Per c-chunk (32 c): x strip (32c x 6rows x pitch76, halo cols zeroed) in smem;
// all 9 shifts read it at (kh,kw) offsets. W prepacked in mma-fragment order,
// streamed via double-buffered register prefetch (LDG.128). B fed as raw f32
// bits (tf32 HW truncation).
// ============================================================================

#define NSTAGES 36

// [stage36][j4][mtile8][lane32][reg4] tf32 bits
static __device__ __align__(128) unsigned WtFrag[NSTAGES * 4 * 8 * 32 * 4];

__global__ void prepack_kernel(const float* __restrict__ W) {
    int idx = blockIdx.x * 256 + threadIdx.x;
    if (idx >= NSTAGES * 4096) return;
    int reg  = idx & 3;
    int lane = (idx >> 2) & 31;
    int mt   = (idx >> 7) & 7;
    int j    = (idx >> 10) & 3;
    int s    = idx >> 12;            // stage = shift*4 + chunk
    int shift = s >> 2;
    int chunk = s & 3;
    int dr = (reg & 1) ? 8 : 0;
    int dk = (reg & 2) ? 4 : 0;
    int r  = (lane >> 2) + dr;
    int kc = (lane & 3) + dk;
    int k  = mt * 16 + r;
    int c  = chunk * 32 + j * 8 + kc;
    float v = W[k * 1152 + c * 9 + shift];
    unsigned u;
    asm("cvt.rna.tf32.f32 %0, %1;" : "=r"(u) : "f"(v));
    WtFrag[idx] = u;
}

// x strip: [c 0..31][row 0..5][col 0..75]; data cols 4..67 (q+4), halos 3 & 68.
#define XS_PITCH  76
#define XS_ROWS   6
#define XS_BUF_F  (32 * XS_ROWS * XS_PITCH)   // 14592 floats
#define XS_BUF_B  (XS_BUF_F * 4)              // 58368 bytes
#define DYN_SMEM  (2 * XS_BUF_B)              // 116736

__device__ __forceinline__ uint32_t smem_u32(const void* p) {
    uint32_t a;
    asm("{ .reg .u64 t; cvta.to.shared.u64 t, %1; cvt.u32.u64 %0, t; }" : "=r"(a) : "l"(p));
    return a;
}

__device__ __forceinline__ void mma_tf32(float* c, const unsigned* a, const unsigned* b) {
    asm volatile(
        "mma.sync.aligned.m16n8k8.row.col.f32.tf32.tf32.f32 "
        "{%0,%1,%2,%3}, {%4,%5,%6,%7}, {%8,%9}, {%0,%1,%2,%3};"
        : "+f"(c[0]), "+f"(c[1]), "+f"(c[2]), "+f"(c[3])
        : "r"(a[0]), "r"(a[1]), "r"(a[2]), "r"(a[3]), "r"(b[0]), "r"(b[1]));
}

__global__ __launch_bounds__(256, 1)
void conv_mma_kernel(const float* __restrict__ x,
                     const float* __restrict__ per,
                     float* __restrict__ out) {
    extern __shared__ char smem[];
    const uint32_t sb = smem_u32(smem);

    const int tid  = threadIdx.x;
    const int lane = tid & 31;
    const int w    = tid >> 5;
    const int wm   = w >> 2;           // 0..1 : k base wm*64
    const int wn   = w & 3;            // 0..3 : p-row index within CTA
    const int gid  = lane >> 2;        // 0..7
    const int tig  = lane & 3;         // 0..3

    const int n  = blockIdx.x >> 4;
    const int p0 = (blockIdx.x & 15) << 2;   // 4 p-rows per CTA

    const float* xn = x + (size_t)n * 128 * 4096;

    // ---- zero halo columns (cols 3 and 68 of every (c,row), both buffers) ----
    for (int idx = tid; idx < 2 * 32 * XS_ROWS; idx += 256) {
        const int buf = idx >= 32 * XS_ROWS;
        const int rem = buf ? idx - 32 * XS_ROWS : idx;
        const uint32_t a = sb + buf * XS_BUF_B + rem * (XS_PITCH * 4);
        asm volatile("st.shared.f32 [%0], %1;" :: "r"(a + 3 * 4), "f"(0.f));
        asm volatile("st.shared.f32 [%0], %1;" :: "r"(a + 68 * 4), "f"(0.f));
    }

    // ---- chunk prefetch: 6 rows x 2 x 16B cp.async per thread ----
    const int f_c  = tid >> 3;          // 0..31 c within chunk
    const int f_q0 = (tid & 7) << 3;    // 0,8,..,56

    auto prefetch = [&](int chunk, int buf) {
        const float* srcc = xn + (size_t)((chunk << 5) + f_c) * 4096 + f_q0;
        const uint32_t dstc = sb + buf * XS_BUF_B +
                              ((f_c * XS_ROWS) * XS_PITCH + 4 + f_q0) * 4;
        #pragma unroll
        for (int r = 0; r < XS_ROWS; r++) {
            const int row = p0 - 1 + r;
            const int pb = ((unsigned)row < 64u) ? 16 : 0;
            const float* src = srcc + row * 64;
            const uint32_t dst = dstc + r * (XS_PITCH * 4);
            asm volatile("cp.async.cg.shared.global [%0], [%1], 16, %2;"
                         :: "r"(dst), "l"(src), "r"(pb));
            asm volatile("cp.async.cg.shared.global [%0], [%1], 16, %2;"
                         :: "r"(dst + 16), "l"(src + 4), "r"(pb));
        }
        asm volatile("cp.async.commit_group;");
    };

    prefetch(0, 0);
    prefetch(1, 1);

    float acc[2][4][4][4];
    #pragma unroll
    for (int nx = 0; nx < 2; nx++)
        #pragma unroll
        for (int mt = 0; mt < 4; mt++)
            #pragma unroll
            for (int nt = 0; nt < 4; nt++)
                #pragma unroll
                for (int e = 0; e < 4; e++) acc[nx][mt][nt][e] = 0.f;

    for (int chunk = 0; chunk < 4; chunk++) {
        if (chunk < 3) asm volatile("cp.async.wait_group 1;");
        else           asm volatile("cp.async.wait_group 0;");
        __syncthreads();

        const uint32_t xb = sb + (chunk & 1) * XS_BUF_B;
        // B base (floats): (tig*6 + wn)*76 + 4 + gid   (c=tig, row=wn, col 4+gid)
        const uint32_t bbase = xb + ((tig * XS_ROWS + wn) * XS_PITCH + 4 + gid) * 4;
        const uint4* abase = (const uint4*)WtFrag + (chunk << 10) + (wm << 7) + lane;

        unsigned areg[2][4][4];
        #pragma unroll
        for (int mt = 0; mt < 4; mt++) {
            uint4 v = __ldg(abase + mt * 32);
            areg[0][mt][0] = v.x; areg[0][mt][1] = v.y;
            areg[0][mt][2] = v.z; areg[0][mt][3] = v.w;
        }

        #pragma unroll
        for (int jj = 0; jj < 36; jj++) {
            const int shift = jj >> 2, j = jj & 3;
            const int kh = shift / 3, kw = shift - 3 * kh;
            const int cur = jj & 1, nxt = cur ^ 1;

            if (jj < 35) {
                const int jn = jj + 1;
                const int aoff = (jn >> 2) * 4096 + (jn & 3) * 256;  // uint4 units
                #pragma unroll
                for (int mt = 0; mt < 4; mt++) {
                    uint4 v = __ldg(abase + aoff + mt * 32);
                    areg[nxt][mt][0] = v.x; areg[nxt][mt][1] = v.y;
                    areg[nxt][mt][2] = v.z; areg[nxt][mt][3] = v.w;
                }
            }

            // shift+j offset in bytes: (kh*76 + kw-1)*4 + j * (8c * 6*76*4)
            const uint32_t bsj = bbase + (kh * XS_PITCH + kw - 1) * 4 + j * 14592;

            #pragma unroll
            for (int nx = 0; nx < 2; nx++) {
                const uint32_t bq = bsj + nx * 128;   // q0 = nx*32 floats
                unsigned b[4][2];
                #pragma unroll
                for (int nt = 0; nt < 4; nt++) {
                    asm volatile("ld.shared.b32 %0, [%1];" : "=r"(b[nt][0])
                                 : "r"(bq + (nt << 5)));
                    asm volatile("ld.shared.b32 %0, [%1];" : "=r"(b[nt][1])
                                 : "r"(bq + (nt << 5) + 7296));   // c+4
                }
                #pragma unroll
                for (int mt = 0; mt < 4; mt++)
                    #pragma unroll
                    for (int nt = 0; nt < 4; nt++)
                        mma_tf32(acc[nx][mt][nt], areg[cur][mt], b[nt]);
            }
        }

        __syncthreads();
        if (chunk + 2 < 4) prefetch(chunk + 2, chunk & 1);
    }

    // ---- epilogue: +perturbs, store ----
    const size_t nbase = (size_t)n * 128 * 4096;
    const int prow = p0 + wn;
    #pragma unroll
    for (int nx = 0; nx < 2; nx++) {
        #pragma unroll
        for (int mt = 0; mt < 4; mt++) {
            #pragma unroll
            for (int nt = 0; nt < 4; nt++) {
                const int q = (nx << 5) + (nt << 3) + (tig << 1);
                #pragma unroll
                for (int h = 0; h < 2; h++) {
                    const int k = (wm << 6) + (mt << 4) + gid + (h << 3);
                    const size_t o = nbase + (size_t)k * 4096 + prow * 64 + q;
                    float2 pv = *reinterpret_cast<const float2*>(per + o);
                    float2 ov;
                    ov.x = acc[nx][mt][nt][h * 2 + 0] + pv.x;
                    ov.y = acc[nx][mt][nt][h * 2 + 1] + pv.y;
                    *reinterpret_cast<float2*>(out + o) = ov;
                }
            }
        }
    }
}

extern "C" void kernel_launch(void* const* d_in, const int* in_sizes, int n_in,
                              void* d_out, int out_size) {
    const float* x   = (const float*)d_in[0];   // (32,128,64,64)
    const float* W   = (const float*)d_in[1];   // (128,1152)
    const float* per = (const float*)d_in[2];   // (32,128,64,64)
    float* out = (float*)d_out;

    cudaFuncSetAttribute(conv_mma_kernel,
                         cudaFuncAttributeMaxDynamicSharedMemorySize, DYN_SMEM);

    prepack_kernel<<<(NSTAGES * 4096 + 255) / 256, 256>>>(W);
    conv_mma_kernel<<<512, 256, DYN_SMEM>>>(x, per, out);
}